// round 10
// baseline (speedup 1.0000x reference)
#include <cuda_runtime.h>
#include <cuda_bf16.h>
#include <math.h>
#include <stdint.h>

#define DIM   1024
#define HID   4096
#define NROWS 32768   // 4 * 8192 tokens

// ---------------- scratch (static __device__ — no allocations allowed) ----------------
__device__ __nv_bfloat16 g_w1q[(size_t)HID * DIM];    // quantized w1 codes as bf16 ints
__device__ __nv_bfloat16 g_w2q[(size_t)DIM * HID];
__device__ __nv_bfloat16 g_aq [(size_t)NROWS * DIM];  // quantized LN(x) codes
__device__ float         g_act[(size_t)NROWS * HID];  // GELU output (fp32, pre-2nd-quant)
__device__ float  g_mu  [NROWS];
__device__ float  g_rstd[NROWS];
// g_maxbits starts zeroed (static init); atomicMax with identical inputs each replay is
// idempotent, so no per-call re-init is needed (graph-replay safe, deterministic).
__device__ unsigned g_maxbits[4];  // 0: max|LN|, 1: max|w1|, 2: max|w2|, 3: max|gelu|

// ---------------- small helpers ----------------
__device__ __forceinline__ float gelu_erf(float y) {
    return 0.5f * y * (1.0f + erff(y * 0.70710678118654752440f));
}

__device__ __forceinline__ unsigned smem_u32(const void* p) {
    return (unsigned)__cvta_generic_to_shared(p);
}

__device__ __forceinline__ void cpasync16(unsigned saddr, const void* gmem) {
    asm volatile("cp.async.cg.shared.global [%0], [%1], 16;\n"
                 :: "r"(saddr), "l"(__cvta_generic_to_global(gmem)));
}
#define CP_COMMIT() asm volatile("cp.async.commit_group;\n" ::: "memory")
#define CP_WAIT1()  asm volatile("cp.async.wait_group 1;\n" ::: "memory")
#define CP_WAIT0()  asm volatile("cp.async.wait_group 0;\n" ::: "memory")

// SW128 swizzle: off ^ ((off>>3)&0x70). For off = r*128 + c (c<128) this equals
// r*128 + (c ^ ((r&7)*16)); k16-slice addresses differ only by XOR ks*32.
__device__ __forceinline__ uint32_t sw128(uint32_t off) {
    return off ^ ((off >> 3) & 0x70);
}

__device__ __forceinline__ void ldsm4(unsigned* r, unsigned saddr) {
    asm volatile("ldmatrix.sync.aligned.m8n8.x4.shared.b16 {%0,%1,%2,%3}, [%4];\n"
                 : "=r"(r[0]), "=r"(r[1]), "=r"(r[2]), "=r"(r[3]) : "r"(saddr));
}

__device__ __forceinline__ void mma16816(float* c, const unsigned* a, unsigned b0, unsigned b1) {
    asm volatile(
        "mma.sync.aligned.m16n8k16.row.col.f32.bf16.bf16.f32 "
        "{%0,%1,%2,%3}, {%4,%5,%6,%7}, {%8,%9}, {%0,%1,%2,%3};\n"
        : "+f"(c[0]), "+f"(c[1]), "+f"(c[2]), "+f"(c[3])
        : "r"(a[0]), "r"(a[1]), "r"(a[2]), "r"(a[3]), "r"(b0), "r"(b1));
}

__device__ __forceinline__ __nv_bfloat16 quant_code_bf(float v, float inv_s) {
    float q = rintf(fminf(fmaxf(v * inv_s, -1.f), 1.f) * 127.f);
    return __float2bfloat16_rn(q);   // integer in [-127,127]: exact in bf16
}

__device__ __forceinline__ uint32_t quant_pair(float v0, float v1, float inv_s) {
    __nv_bfloat162 p;
    p.x = quant_code_bf(v0, inv_s);
    p.y = quant_code_bf(v1, inv_s);
    return *(uint32_t*)&p;
}

// ---------------- per-tensor abs-max of BOTH weights (launch 0) ----------------
__global__ void __launch_bounds__(256) k_maxabs2(const float4* __restrict__ w1,
                                                 const float4* __restrict__ w2, int n4) {
    const float4* p = (blockIdx.x < gridDim.x / 2) ? w1 : w2;
    int slot = (blockIdx.x < gridDim.x / 2) ? 1 : 2;
    int b0 = (blockIdx.x < gridDim.x / 2) ? blockIdx.x : blockIdx.x - gridDim.x / 2;
    float m = 0.f;
    for (int i = b0 * blockDim.x + threadIdx.x; i < n4; i += (gridDim.x / 2) * blockDim.x) {
        float4 v = p[i];
        m = fmaxf(m, fmaxf(fmaxf(fabsf(v.x), fabsf(v.y)), fmaxf(fabsf(v.z), fabsf(v.w))));
    }
    #pragma unroll
    for (int o = 16; o; o >>= 1) m = fmaxf(m, __shfl_xor_sync(0xffffffffu, m, o));
    __shared__ float sm[8];
    if ((threadIdx.x & 31) == 0) sm[threadIdx.x >> 5] = m;
    __syncthreads();
    if (threadIdx.x == 0) {
        #pragma unroll
        for (int i = 1; i < 8; i++) m = fmaxf(m, sm[i]);
        m = fmaxf(m, sm[0]);
        atomicMax(&g_maxbits[slot], __float_as_uint(m));
    }
}

// ---------------- LayerNorm stats + global max|LN(x)| (launch 1) --------------
__global__ void __launch_bounds__(256) k_ln(const float* __restrict__ x,
                                            const float* __restrict__ gamma,
                                            const float* __restrict__ beta) {
    int t = threadIdx.x;
    int w = t >> 5;
    __shared__ float a1[8], a2[8];
    __shared__ float s_mu, s_rstd;
    float4 gm = ((const float4*)gamma)[t];
    float4 bt = ((const float4*)beta)[t];
    float gmax = 0.f;
    for (int r = 0; r < 8; r++) {
        int row = blockIdx.x * 8 + r;
        float4 v = ((const float4*)(x + (size_t)row * DIM))[t];
        float s1 = v.x + v.y + v.z + v.w;
        float s2 = v.x * v.x + v.y * v.y + v.z * v.z + v.w * v.w;
        #pragma unroll
        for (int o = 16; o; o >>= 1) {
            s1 += __shfl_xor_sync(0xffffffffu, s1, o);
            s2 += __shfl_xor_sync(0xffffffffu, s2, o);
        }
        if ((t & 31) == 0) { a1[w] = s1; a2[w] = s2; }
        __syncthreads();
        if (t == 0) {
            float S1 = 0.f, S2 = 0.f;
            #pragma unroll
            for (int i = 0; i < 8; i++) { S1 += a1[i]; S2 += a2[i]; }
            float mu   = S1 * (1.0f / DIM);
            float var  = S2 * (1.0f / DIM) - mu * mu;
            float rstd = rsqrtf(var + 1e-5f);
            s_mu = mu; s_rstd = rstd;
            g_mu[row] = mu; g_rstd[row] = rstd;
        }
        __syncthreads();
        float mu = s_mu, rs = s_rstd;
        float h0 = (v.x - mu) * rs * gm.x + bt.x;
        float h1 = (v.y - mu) * rs * gm.y + bt.y;
        float h2 = (v.z - mu) * rs * gm.z + bt.z;
        float h3 = (v.w - mu) * rs * gm.w + bt.w;
        gmax = fmaxf(gmax, fmaxf(fmaxf(fabsf(h0), fabsf(h1)), fmaxf(fabsf(h2), fabsf(h3))));
        __syncthreads();
    }
    #pragma unroll
    for (int o = 16; o; o >>= 1) gmax = fmaxf(gmax, __shfl_xor_sync(0xffffffffu, gmax, o));
    if ((t & 31) == 0) a1[w] = gmax;
    __syncthreads();
    if (t == 0) {
        float m = a1[0];
        #pragma unroll
        for (int i = 1; i < 8; i++) m = fmaxf(m, a1[i]);
        atomicMax(&g_maxbits[0], __float_as_uint(m));
    }
}

// ------- quantize BOTH weights + LN activations in ONE kernel (launch 2) -------
__global__ void __launch_bounds__(256) k_quant(const float4* __restrict__ w1,
                                               const float4* __restrict__ w2, int n4,
                                               const float* __restrict__ x,
                                               const float* __restrict__ gamma,
                                               const float* __restrict__ beta) {
    int i = blockIdx.x * 256 + threadIdx.x;
    if (i < 2 * n4) {
        const float4* w; __nv_bfloat16* out; int slot;
        if (i < n4) { w = w1; out = g_w1q; slot = 1; }
        else        { w = w2; out = g_w2q; slot = 2; i -= n4; }
        float inv_s = 1.0f / __uint_as_float(g_maxbits[slot]);
        float4 v = w[i];
        ushort4 u;
        u.x = __bfloat16_as_ushort(quant_code_bf(v.x, inv_s));
        u.y = __bfloat16_as_ushort(quant_code_bf(v.y, inv_s));
        u.z = __bfloat16_as_ushort(quant_code_bf(v.z, inv_s));
        u.w = __bfloat16_as_ushort(quant_code_bf(v.w, inv_s));
        ((ushort4*)out)[i] = u;
    } else {
        i -= 2 * n4;
        int row = i >> 8;
        int c4  = i & 255;
        float inv_s = 1.0f / __uint_as_float(g_maxbits[0]);
        float mu = g_mu[row], r = g_rstd[row];
        float4 v  = ((const float4*)x)[i];
        float4 gm = ((const float4*)gamma)[c4];
        float4 bt = ((const float4*)beta)[c4];
        ushort4 u;
        u.x = __bfloat16_as_ushort(quant_code_bf((v.x - mu) * r * gm.x + bt.x, inv_s));
        u.y = __bfloat16_as_ushort(quant_code_bf((v.y - mu) * r * gm.y + bt.y, inv_s));
        u.z = __bfloat16_as_ushort(quant_code_bf((v.z - mu) * r * gm.z + bt.z, inv_s));
        u.w = __bfloat16_as_ushort(quant_code_bf((v.w - mu) * r * gm.w + bt.w, inv_s));
        ((ushort4*)g_aq)[i] = u;
    }
}

// ===== bf16 HMMA GEMM: CTA 128x128, warp tile 64x32, 3-stage, 2 CTAs/SM ============
// GELU=true  (GEMM1): A = g_aq codes via cp.async; epilogue gelu->g_act fp32 + max.
// GELU=false (GEMM2): A = g_act fp32, quantized to codes AT LOAD (k_hquant fused in);
//                     only B uses cp.async groups.
#define BK 64
#define STAGE_A (128 * 128)            // 16 KB (128 rows x 128B)
#define STAGE_BYTES (2 * STAGE_A)      // A + B per stage = 32 KB
#define GEMM_DYN (3 * STAGE_BYTES)     // 96 KB

template<bool GELU, int NFULL, int K>
__global__ void __launch_bounds__(256, 2) k_gemm(const float* __restrict__ bias,
                                                 float* __restrict__ out) {
    constexpr int KT = K / BK;
    const __nv_bfloat16* __restrict__ B = GELU ? g_w1q : g_w2q;

    extern __shared__ uint8_t dyn[];
    const uint32_t base = smem_u32(dyn);   // dynamic smem is >=1KB aligned

    const int tid  = threadIdx.x;
    const int lane = tid & 31;
    const int wid  = tid >> 5;
    const int m_w  = (wid & 1) * 64;       // 2 warp rows of 64
    const int n_w  = (wid >> 1) * 32;      // 4 warp cols of 32
    const int mBase = blockIdx.y * 128;
    const int nBase = blockIdx.x * 128;

    const uint8_t* Bgb = (const uint8_t*)(B + (size_t)nBase * K);
    const int rowBytes = K * 2;

    // loader coords (per thread): chunk c = tid + i*256 -> row rr+i*32, col (tid&7)
    const int rr  = tid >> 3;              // row base
    const int c16 = (tid & 7) * 16;        // byte col within 128B code row
    // fp32 A source (GEMM2 only)
    const float* Agf = g_act + (size_t)(mBase + rr) * K + (tid & 7) * 8;
    const float inv_h = GELU ? 0.f : (1.0f / __uint_as_float(g_maxbits[3]));
    const uint8_t* Agb = (const uint8_t*)(g_aq + (size_t)mBase * K) +
                         (size_t)rr * rowBytes + c16;   // bf16 A source (GEMM1 only)

    float acc[4][4][4];                    // 64 regs
    #pragma unroll
    for (int i = 0; i < 4; i++)
        #pragma unroll
        for (int j = 0; j < 4; j++)
            #pragma unroll
            for (int r = 0; r < 4; r++) acc[i][j][r] = 0.f;

    // B cp.async loads (both modes)
    auto loadB = [&](int kt, int s) {
        uint32_t b0 = base + s * STAGE_BYTES + STAGE_A;
        int k0b = kt * (BK * 2);
        #pragma unroll
        for (int i = 0; i < 4; i++) {
            int r = rr + i * 32;
            uint32_t off = (uint32_t)r * 128 + c16;
            cpasync16(b0 + sw128(off), Bgb + (size_t)r * rowBytes + k0b + c16);
        }
    };
    // A cp.async loads (GEMM1)
    auto loadA = [&](int kt, int s) {
        uint32_t a0 = base + s * STAGE_BYTES;
        int k0b = kt * (BK * 2);
        #pragma unroll
        for (int i = 0; i < 4; i++) {
            int r = rr + i * 32;
            uint32_t off = (uint32_t)r * 128 + c16;
            cpasync16(a0 + sw128(off), Agb + (size_t)(i * 32) * rowBytes + k0b);
        }
    };
    // A fp32 load half (GEMM2): i in {i0, i0+1}
    auto ldgA_half = [&](int kt, int i0, float4* aR) {
        #pragma unroll
        for (int j = 0; j < 2; j++) {
            const float* p = Agf + (size_t)((i0 + j) * 32) * K + kt * BK;
            aR[2 * j]     = *(const float4*)p;
            aR[2 * j + 1] = *(const float4*)(p + 4);
        }
    };
    auto stsA_half = [&](int s, int i0, const float4* aR) {
        uint32_t a0 = s * STAGE_BYTES;
        #pragma unroll
        for (int j = 0; j < 2; j++) {
            int r = rr + (i0 + j) * 32;
            uint32_t off = sw128((uint32_t)r * 128 + c16);
            uint4 u;
            u.x = quant_pair(aR[2*j].x,   aR[2*j].y,   inv_h);
            u.y = quant_pair(aR[2*j].z,   aR[2*j].w,   inv_h);
            u.z = quant_pair(aR[2*j+1].x, aR[2*j+1].y, inv_h);
            u.w = quant_pair(aR[2*j+1].z, aR[2*j+1].w, inv_h);
            *(uint4*)(dyn + a0 + off) = u;
        }
    };

    // ---- prologue ----
    if (GELU) {
        loadA(0, 0); loadB(0, 0); CP_COMMIT();
        loadA(1, 1); loadB(1, 1); CP_COMMIT();
    } else {
        float4 aR[4];
        ldgA_half(0, 0, aR); stsA_half(0, 0, aR);
        ldgA_half(0, 2, aR); stsA_half(0, 2, aR);
        ldgA_half(1, 0, aR); stsA_half(1, 0, aR);
        ldgA_half(1, 2, aR); stsA_half(1, 2, aR);
        loadB(0, 0); CP_COMMIT();
        loadB(1, 1); CP_COMMIT();
    }

    // hoisted swizzled ldsm offsets; per-ks address = off ^ (ks*32)
    const int lr  = lane & 15;
    const uint32_t l16 = (lane >> 4) * 16;
    uint32_t a_off[4], b_off[2];
    #pragma unroll
    for (int mi = 0; mi < 4; mi++) {
        uint32_t r = m_w + mi * 16 + lr;
        a_off[mi] = r * 128 + (l16 ^ ((r & 7) * 16));
    }
    #pragma unroll
    for (int ni = 0; ni < 2; ni++) {
        uint32_t r = n_w + ni * 16 + lr;
        b_off[ni] = STAGE_A + r * 128 + (l16 ^ ((r & 7) * 16));
    }

    int stage = 0;
    for (int kt = 0; kt < KT; ++kt) {
        if (kt == KT - 1) { CP_WAIT0(); } else { CP_WAIT1(); }
        __syncthreads();   // stage kt visible; stage (kt-1)%3 compute finished
        uint32_t sb = base + stage * STAGE_BYTES;
        const bool pf = (kt + 2 < KT);
        const int  ps = (kt + 2) % 3;

        if (GELU) {
            if (pf) { loadA(kt + 2, ps); loadB(kt + 2, ps); CP_COMMIT(); }
            #pragma unroll
            for (int ks = 0; ks < 4; ++ks) {
                const uint32_t xv = ks * 32;
                unsigned af[4][4], bfr[2][4];
                #pragma unroll
                for (int mi = 0; mi < 4; mi++) ldsm4(af[mi], sb + (a_off[mi] ^ xv));
                #pragma unroll
                for (int ni = 0; ni < 2; ni++) ldsm4(bfr[ni], sb + (b_off[ni] ^ xv));
                #pragma unroll
                for (int mi = 0; mi < 4; mi++)
                    #pragma unroll
                    for (int nj = 0; nj < 4; nj++)
                        mma16816(acc[mi][nj], af[mi],
                                 bfr[nj >> 1][nj & 1], bfr[nj >> 1][2 + (nj & 1)]);
            }
        } else {
            float4 aR[4];
            if (pf) { ldgA_half(kt + 2, 0, aR); loadB(kt + 2, ps); CP_COMMIT(); }
            #pragma unroll
            for (int ks = 0; ks < 4; ++ks) {
                const uint32_t xv = ks * 32;
                unsigned af[4][4], bfr[2][4];
                #pragma unroll
                for (int mi = 0; mi < 4; mi++) ldsm4(af[mi], sb + (a_off[mi] ^ xv));
                #pragma unroll
                for (int ni = 0; ni < 2; ni++) ldsm4(bfr[ni], sb + (b_off[ni] ^ xv));
                #pragma unroll
                for (int mi = 0; mi < 4; mi++)
                    #pragma unroll
                    for (int nj = 0; nj < 4; nj++)
                        mma16816(acc[mi][nj], af[mi],
                                 bfr[nj >> 1][nj & 1], bfr[nj >> 1][2 + (nj & 1)]);
                if (ks == 1 && pf) {        // mid-loop: flush half1, fetch half2
                    stsA_half(ps, 0, aR);
                    ldgA_half(kt + 2, 2, aR);
                }
            }
            if (pf) stsA_half(ps, 2, aR);
        }
        stage = (stage + 1 == 3) ? 0 : stage + 1;
    }
    __syncthreads();   // last stage compute done before smem reuse below

    // ---- epilogue ----
    if (GELU) {
        float scale = __uint_as_float(g_maxbits[0]) * __uint_as_float(g_maxbits[1])
                    * (1.0f / 16129.0f);
        float lmax = 0.f;
        #pragma unroll
        for (int mi = 0; mi < 4; mi++) {
            int r0 = mBase + m_w + mi * 16 + (lane >> 2);
            #pragma unroll
            for (int nj = 0; nj < 4; nj++) {
                int c0 = nBase + n_w + nj * 8 + (lane & 3) * 2;
                float b0 = bias[c0], b1 = bias[c0 + 1];
                float g00 = gelu_erf(acc[mi][nj][0] * scale + b0);
                float g01 = gelu_erf(acc[mi][nj][1] * scale + b1);
                float g10 = gelu_erf(acc[mi][nj][2] * scale + b0);
                float g11 = gelu_erf(acc[mi][nj][3] * scale + b1);
                lmax = fmaxf(lmax, fmaxf(fmaxf(fabsf(g00), fabsf(g01)),
                                         fmaxf(fabsf(g10), fabsf(g11))));
                *(float2*)&g_act[(size_t)r0 * NFULL + c0]       = make_float2(g00, g01);
                *(float2*)&g_act[(size_t)(r0 + 8) * NFULL + c0] = make_float2(g10, g11);
            }
        }
        #pragma unroll
        for (int o = 16; o; o >>= 1) lmax = fmaxf(lmax, __shfl_xor_sync(0xffffffffu, lmax, o));
        float* red = (float*)dyn;    // reuse tile smem (sync above)
        if (lane == 0) red[wid] = lmax;
        __syncthreads();
        if (tid == 0) {
            float m = red[0];
            #pragma unroll
            for (int i = 1; i < 8; i++) m = fmaxf(m, red[i]);
            atomicMax(&g_maxbits[3], __float_as_uint(m));
        }
    } else {
        float scale = __uint_as_float(g_maxbits[3]) * __uint_as_float(g_maxbits[2])
                    * (1.0f / 16129.0f);
        #pragma unroll
        for (int mi = 0; mi < 4; mi++) {
            int r0 = mBase + m_w + mi * 16 + (lane >> 2);
            #pragma unroll
            for (int nj = 0; nj < 4; nj++) {
                int c0 = nBase + n_w + nj * 8 + (lane & 3) * 2;
                float b0 = bias[c0], b1 = bias[c0 + 1];
                float2 y0 = make_float2(acc[mi][nj][0] * scale + b0,
                                        acc[mi][nj][1] * scale + b1);
                float2 y1 = make_float2(acc[mi][nj][2] * scale + b0,
                                        acc[mi][nj][3] * scale + b1);
                *(float2*)&out[(size_t)r0 * NFULL + c0]       = y0;
                *(float2*)&out[(size_t)(r0 + 8) * NFULL + c0] = y1;
            }
        }
    }
}

// ---------------- launch ----------------
extern "C" void kernel_launch(void* const* d_in, const int* in_sizes, int n_in,
                              void* d_out, int out_size) {
    const float* x     = (const float*)d_in[0];
    const float* gamma = (const float*)d_in[1];
    const float* beta  = (const float*)d_in[2];
    const float* w1    = (const float*)d_in[3];
    const float* b1    = (const float*)d_in[4];
    const float* w2    = (const float*)d_in[5];
    const float* b2    = (const float*)d_in[6];
    float* out = (float*)d_out;

    const int WN4 = HID * DIM / 4;  // 1048576 float4s per weight matrix

    cudaFuncSetAttribute(k_gemm<true,  HID, DIM>,
                         cudaFuncAttributeMaxDynamicSharedMemorySize, GEMM_DYN);
    cudaFuncSetAttribute(k_gemm<false, DIM, HID>,
                         cudaFuncAttributeMaxDynamicSharedMemorySize, GEMM_DYN);

    // launch 0: weight abs-max
    k_maxabs2<<<1024, 256>>>((const float4*)w1, (const float4*)w2, WN4);
    // launch 1: LN stats + max|LN|
    k_ln<<<NROWS / 8, 256>>>(x, gamma, beta);
    // launch 2: quantize w1, w2, and LN(x)
    {
        int wblocks = 2 * WN4 / 256;                    // 8192
        int ablocks = NROWS * (DIM / 4) / 256;          // 32768
        k_quant<<<wblocks + ablocks, 256>>>((const float4*)w1, (const float4*)w2, WN4,
                                            x, gamma, beta);
    }
    // launch 3 (ncu-profiled slot): GEMM1 -> gelu -> g_act (fp32), track max|gelu|
    k_gemm<true, HID, DIM><<<dim3(HID / 128, NROWS / 128), 256, GEMM_DYN>>>(b1, nullptr);
    // launch 4: GEMM2 (A quantized at load from g_act) -> d_out (fp32)
    k_gemm<false, DIM, HID><<<dim3(DIM / 128, NROWS / 128), 256, GEMM_DYN>>>(b2, out);
}

// round 11
// speedup vs baseline: 1.0710x; 1.0710x over previous
#include <cuda_runtime.h>
#include <cuda_bf16.h>
#include <math.h>
#include <stdint.h>

#define DIM   1024
#define HID   4096
#define NROWS 32768   // 4 * 8192 tokens

// ---------------- scratch (static __device__ — no allocations allowed) ----------------
__device__ __nv_bfloat16 g_w1q[(size_t)HID * DIM];    // quantized w1 codes as bf16 ints
__device__ __nv_bfloat16 g_w2q[(size_t)DIM * HID];
__device__ __nv_bfloat16 g_aq [(size_t)NROWS * DIM];  // quantized LN(x) codes
__device__ float         g_act[(size_t)NROWS * HID];  // GELU output (fp32, pre-2nd-quant)
__device__ __nv_bfloat16 g_hq [(size_t)NROWS * HID];  // quantized hidden codes
__device__ float  g_mu  [NROWS];
__device__ float  g_rstd[NROWS];
// g_maxbits starts zeroed (static init); atomicMax with identical inputs each replay is
// idempotent, so no per-call re-init is needed (graph-replay safe, deterministic).
__device__ unsigned g_maxbits[4];  // 0: max|LN|, 1: max|w1|, 2: max|w2|, 3: max|gelu|

// ---------------- small helpers ----------------
__device__ __forceinline__ float gelu_erf(float y) {
    return 0.5f * y * (1.0f + erff(y * 0.70710678118654752440f));
}

__device__ __forceinline__ unsigned smem_u32(const void* p) {
    return (unsigned)__cvta_generic_to_shared(p);
}

__device__ __forceinline__ void cpasync16(unsigned saddr, const void* gmem) {
    asm volatile("cp.async.cg.shared.global [%0], [%1], 16;\n"
                 :: "r"(saddr), "l"(__cvta_generic_to_global(gmem)));
}
#define CP_COMMIT() asm volatile("cp.async.commit_group;\n" ::: "memory")
#define CP_WAIT1()  asm volatile("cp.async.wait_group 1;\n" ::: "memory")
#define CP_WAIT0()  asm volatile("cp.async.wait_group 0;\n" ::: "memory")

// SW128 swizzle: off ^ ((off>>3)&0x70). For off = r*128 + c (c<128) this equals
// r*128 + (c ^ ((r&7)*16)); k16-slice addresses differ only by XOR ks*32.
__device__ __forceinline__ uint32_t sw128(uint32_t off) {
    return off ^ ((off >> 3) & 0x70);
}

__device__ __forceinline__ void ldsm4(unsigned* r, unsigned saddr) {
    asm volatile("ldmatrix.sync.aligned.m8n8.x4.shared.b16 {%0,%1,%2,%3}, [%4];\n"
                 : "=r"(r[0]), "=r"(r[1]), "=r"(r[2]), "=r"(r[3]) : "r"(saddr));
}

__device__ __forceinline__ void mma16816(float* c, const unsigned* a, unsigned b0, unsigned b1) {
    asm volatile(
        "mma.sync.aligned.m16n8k16.row.col.f32.bf16.bf16.f32 "
        "{%0,%1,%2,%3}, {%4,%5,%6,%7}, {%8,%9}, {%0,%1,%2,%3};\n"
        : "+f"(c[0]), "+f"(c[1]), "+f"(c[2]), "+f"(c[3])
        : "r"(a[0]), "r"(a[1]), "r"(a[2]), "r"(a[3]), "r"(b0), "r"(b1));
}

__device__ __forceinline__ __nv_bfloat16 quant_code_bf(float v, float inv_s) {
    float q = rintf(fminf(fmaxf(v * inv_s, -1.f), 1.f) * 127.f);
    return __float2bfloat16_rn(q);   // integer in [-127,127]: exact in bf16
}

// ---------------- per-tensor abs-max of BOTH weights (launch 0) ----------------
__global__ void __launch_bounds__(256) k_maxabs2(const float4* __restrict__ w1,
                                                 const float4* __restrict__ w2, int n4) {
    const float4* p = (blockIdx.x < gridDim.x / 2) ? w1 : w2;
    int slot = (blockIdx.x < gridDim.x / 2) ? 1 : 2;
    int b0 = (blockIdx.x < gridDim.x / 2) ? blockIdx.x : blockIdx.x - gridDim.x / 2;
    float m = 0.f;
    for (int i = b0 * blockDim.x + threadIdx.x; i < n4; i += (gridDim.x / 2) * blockDim.x) {
        float4 v = __ldcs(p + i);
        m = fmaxf(m, fmaxf(fmaxf(fabsf(v.x), fabsf(v.y)), fmaxf(fabsf(v.z), fabsf(v.w))));
    }
    #pragma unroll
    for (int o = 16; o; o >>= 1) m = fmaxf(m, __shfl_xor_sync(0xffffffffu, m, o));
    __shared__ float sm[8];
    if ((threadIdx.x & 31) == 0) sm[threadIdx.x >> 5] = m;
    __syncthreads();
    if (threadIdx.x == 0) {
        #pragma unroll
        for (int i = 1; i < 8; i++) m = fmaxf(m, sm[i]);
        m = fmaxf(m, sm[0]);
        atomicMax(&g_maxbits[slot], __float_as_uint(m));
    }
}

// ---------------- LayerNorm stats + global max|LN(x)| (launch 1) --------------
__global__ void __launch_bounds__(256) k_ln(const float* __restrict__ x,
                                            const float* __restrict__ gamma,
                                            const float* __restrict__ beta) {
    int t = threadIdx.x;
    int w = t >> 5;
    __shared__ float a1[8], a2[8];
    __shared__ float s_mu, s_rstd;
    float4 gm = ((const float4*)gamma)[t];
    float4 bt = ((const float4*)beta)[t];
    float gmax = 0.f;
    for (int r = 0; r < 8; r++) {
        int row = blockIdx.x * 8 + r;
        float4 v = ((const float4*)(x + (size_t)row * DIM))[t];
        float s1 = v.x + v.y + v.z + v.w;
        float s2 = v.x * v.x + v.y * v.y + v.z * v.z + v.w * v.w;
        #pragma unroll
        for (int o = 16; o; o >>= 1) {
            s1 += __shfl_xor_sync(0xffffffffu, s1, o);
            s2 += __shfl_xor_sync(0xffffffffu, s2, o);
        }
        if ((t & 31) == 0) { a1[w] = s1; a2[w] = s2; }
        __syncthreads();
        if (t == 0) {
            float S1 = 0.f, S2 = 0.f;
            #pragma unroll
            for (int i = 0; i < 8; i++) { S1 += a1[i]; S2 += a2[i]; }
            float mu   = S1 * (1.0f / DIM);
            float var  = S2 * (1.0f / DIM) - mu * mu;
            float rstd = rsqrtf(var + 1e-5f);
            s_mu = mu; s_rstd = rstd;
            g_mu[row] = mu; g_rstd[row] = rstd;
        }
        __syncthreads();
        float mu = s_mu, rs = s_rstd;
        float h0 = (v.x - mu) * rs * gm.x + bt.x;
        float h1 = (v.y - mu) * rs * gm.y + bt.y;
        float h2 = (v.z - mu) * rs * gm.z + bt.z;
        float h3 = (v.w - mu) * rs * gm.w + bt.w;
        gmax = fmaxf(gmax, fmaxf(fmaxf(fabsf(h0), fabsf(h1)), fmaxf(fabsf(h2), fabsf(h3))));
        __syncthreads();
    }
    #pragma unroll
    for (int o = 16; o; o >>= 1) gmax = fmaxf(gmax, __shfl_xor_sync(0xffffffffu, gmax, o));
    if ((t & 31) == 0) a1[w] = gmax;
    __syncthreads();
    if (t == 0) {
        float m = a1[0];
        #pragma unroll
        for (int i = 1; i < 8; i++) m = fmaxf(m, a1[i]);
        atomicMax(&g_maxbits[0], __float_as_uint(m));
    }
}

// ------- quantize BOTH weights + LN activations in ONE kernel (launch 2) -------
__global__ void __launch_bounds__(256) k_quant(const float4* __restrict__ w1,
                                               const float4* __restrict__ w2, int n4,
                                               const float* __restrict__ x,
                                               const float* __restrict__ gamma,
                                               const float* __restrict__ beta) {
    int i = blockIdx.x * 256 + threadIdx.x;
    if (i < 2 * n4) {
        const float4* w; __nv_bfloat16* out; int slot;
        if (i < n4) { w = w1; out = g_w1q; slot = 1; }
        else        { w = w2; out = g_w2q; slot = 2; i -= n4; }
        float inv_s = 1.0f / __uint_as_float(g_maxbits[slot]);
        float4 v = __ldcs(w + i);
        ushort4 u;
        u.x = __bfloat16_as_ushort(quant_code_bf(v.x, inv_s));
        u.y = __bfloat16_as_ushort(quant_code_bf(v.y, inv_s));
        u.z = __bfloat16_as_ushort(quant_code_bf(v.z, inv_s));
        u.w = __bfloat16_as_ushort(quant_code_bf(v.w, inv_s));
        ((ushort4*)out)[i] = u;
    } else {
        i -= 2 * n4;
        int row = i >> 8;
        int c4  = i & 255;
        float inv_s = 1.0f / __uint_as_float(g_maxbits[0]);
        float mu = g_mu[row], r = g_rstd[row];
        float4 v  = ((const float4*)x)[i];
        float4 gm = ((const float4*)gamma)[c4];
        float4 bt = ((const float4*)beta)[c4];
        ushort4 u;
        u.x = __bfloat16_as_ushort(quant_code_bf((v.x - mu) * r * gm.x + bt.x, inv_s));
        u.y = __bfloat16_as_ushort(quant_code_bf((v.y - mu) * r * gm.y + bt.y, inv_s));
        u.z = __bfloat16_as_ushort(quant_code_bf((v.z - mu) * r * gm.z + bt.z, inv_s));
        u.w = __bfloat16_as_ushort(quant_code_bf((v.w - mu) * r * gm.w + bt.w, inv_s));
        ((ushort4*)g_aq)[i] = u;
    }
}

// ------- hidden quantize (GELU fp32 -> bf16 codes), 64B/thread, streaming -------
__global__ void __launch_bounds__(256) k_hquant() {
    size_t b = (size_t)blockIdx.x * 1024 + threadIdx.x;   // 4 float4 per thread
    float inv_s = 1.0f / __uint_as_float(g_maxbits[3]);
    #pragma unroll
    for (int j = 0; j < 4; j++) {
        size_t i = b + (size_t)j * 256;
        float4 v = __ldcs((const float4*)g_act + i);
        ushort4 u;
        u.x = __bfloat16_as_ushort(quant_code_bf(v.x, inv_s));
        u.y = __bfloat16_as_ushort(quant_code_bf(v.y, inv_s));
        u.z = __bfloat16_as_ushort(quant_code_bf(v.z, inv_s));
        u.w = __bfloat16_as_ushort(quant_code_bf(v.w, inv_s));
        __stcs((ushort4*)g_hq + i, u);
    }
}

// ===== bf16 HMMA GEMM: CTA 128x128, warp tile 64x32, 3-stage, 2 CTAs/SM ============
// Both operands via cp.async codes (round-8 structure + round-10 hoisted addressing).
#define BK 64
#define STAGE_A (128 * 128)            // 16 KB (128 rows x 128B)
#define STAGE_BYTES (2 * STAGE_A)      // A + B per stage = 32 KB
#define GEMM_DYN (3 * STAGE_BYTES)     // 96 KB

template<bool GELU, int NFULL, int K>
__global__ void __launch_bounds__(256, 2) k_gemm(const float* __restrict__ bias,
                                                 float* __restrict__ out) {
    constexpr int KT = K / BK;
    const __nv_bfloat16* __restrict__ A = GELU ? g_aq  : g_hq;
    const __nv_bfloat16* __restrict__ B = GELU ? g_w1q : g_w2q;

    extern __shared__ uint8_t dyn[];
    const uint32_t base = smem_u32(dyn);   // dynamic smem is >=1KB aligned

    const int tid  = threadIdx.x;
    const int lane = tid & 31;
    const int wid  = tid >> 5;
    const int m_w  = (wid & 1) * 64;       // 2 warp rows of 64
    const int n_w  = (wid >> 1) * 32;      // 4 warp cols of 32
    const int mBase = blockIdx.y * 128;
    const int nBase = blockIdx.x * 128;

    const int rowBytes = K * 2;
    // per-thread loader base pointers: chunk c = tid + i*256 -> row rr + i*32, col c16
    const int rr  = tid >> 3;
    const int c16 = (tid & 7) * 16;
    const uint8_t* Agb = (const uint8_t*)(A + (size_t)mBase * K) + (size_t)rr * rowBytes + c16;
    const uint8_t* Bgb = (const uint8_t*)(B + (size_t)nBase * K) + (size_t)rr * rowBytes + c16;
    const uint32_t soff = sw128((uint32_t)rr * 128 + c16);   // same pattern each i-step of 32 rows

    float acc[4][4][4];                    // 64 regs
    #pragma unroll
    for (int i = 0; i < 4; i++)
        #pragma unroll
        for (int j = 0; j < 4; j++)
            #pragma unroll
            for (int r = 0; r < 4; r++) acc[i][j][r] = 0.f;

    auto loadTile = [&](int kt, int s) {
        uint32_t a0 = base + s * STAGE_BYTES;
        int k0b = kt * (BK * 2);
        #pragma unroll
        for (int i = 0; i < 4; i++)   // A: rows rr + i*32 (row%8 invariant -> same swizzle)
            cpasync16(a0 + soff + (uint32_t)(i * 32) * 128,
                      Agb + (size_t)(i * 32) * rowBytes + k0b);
        #pragma unroll
        for (int i = 0; i < 4; i++)   // B
            cpasync16(a0 + STAGE_A + soff + (uint32_t)(i * 32) * 128,
                      Bgb + (size_t)(i * 32) * rowBytes + k0b);
    };

    loadTile(0, 0); CP_COMMIT();
    if (KT > 1) { loadTile(1, 1); CP_COMMIT(); }

    // hoisted swizzled ldsm offsets; per-ks address = off ^ (ks*32)
    const int lr  = lane & 15;
    const uint32_t l16 = (lane >> 4) * 16;
    uint32_t a_off[4], b_off[2];
    #pragma unroll
    for (int mi = 0; mi < 4; mi++) {
        uint32_t r = m_w + mi * 16 + lr;
        a_off[mi] = r * 128 + (l16 ^ ((r & 7) * 16));
    }
    #pragma unroll
    for (int ni = 0; ni < 2; ni++) {
        uint32_t r = n_w + ni * 16 + lr;
        b_off[ni] = STAGE_A + r * 128 + (l16 ^ ((r & 7) * 16));
    }

    int stage = 0;
    for (int kt = 0; kt < KT; ++kt) {
        if (kt == KT - 1) { CP_WAIT0(); } else { CP_WAIT1(); }
        __syncthreads();   // stage kt visible; stage (kt-1)%3 compute finished
        if (kt + 2 < KT) { loadTile(kt + 2, (kt + 2) % 3); CP_COMMIT(); }

        uint32_t sb = base + stage * STAGE_BYTES;
        #pragma unroll
        for (int ks = 0; ks < 4; ++ks) {       // 4 x k16 covers BK=64
            const uint32_t xv = ks * 32;
            unsigned af[4][4], bfr[2][4];
            #pragma unroll
            for (int mi = 0; mi < 4; mi++) ldsm4(af[mi], sb + (a_off[mi] ^ xv));
            #pragma unroll
            for (int ni = 0; ni < 2; ni++) ldsm4(bfr[ni], sb + (b_off[ni] ^ xv));
            #pragma unroll
            for (int mi = 0; mi < 4; mi++)
                #pragma unroll
                for (int nj = 0; nj < 4; nj++)
                    mma16816(acc[mi][nj], af[mi],
                             bfr[nj >> 1][nj & 1], bfr[nj >> 1][2 + (nj & 1)]);
        }
        stage = (stage + 1 == 3) ? 0 : stage + 1;
    }
    __syncthreads();   // last stage compute done before smem reuse below

    // ---- epilogue ----
    if (GELU) {
        float scale = __uint_as_float(g_maxbits[0]) * __uint_as_float(g_maxbits[1])
                    * (1.0f / 16129.0f);
        float lmax = 0.f;
        #pragma unroll
        for (int mi = 0; mi < 4; mi++) {
            int r0 = mBase + m_w + mi * 16 + (lane >> 2);
            #pragma unroll
            for (int nj = 0; nj < 4; nj++) {
                int c0 = nBase + n_w + nj * 8 + (lane & 3) * 2;
                float b0 = bias[c0], b1 = bias[c0 + 1];
                float g00 = gelu_erf(acc[mi][nj][0] * scale + b0);
                float g01 = gelu_erf(acc[mi][nj][1] * scale + b1);
                float g10 = gelu_erf(acc[mi][nj][2] * scale + b0);
                float g11 = gelu_erf(acc[mi][nj][3] * scale + b1);
                lmax = fmaxf(lmax, fmaxf(fmaxf(fabsf(g00), fabsf(g01)),
                                         fmaxf(fabsf(g10), fabsf(g11))));
                __stcs((float2*)&g_act[(size_t)r0 * NFULL + c0],       make_float2(g00, g01));
                __stcs((float2*)&g_act[(size_t)(r0 + 8) * NFULL + c0], make_float2(g10, g11));
            }
        }
        #pragma unroll
        for (int o = 16; o; o >>= 1) lmax = fmaxf(lmax, __shfl_xor_sync(0xffffffffu, lmax, o));
        float* red = (float*)dyn;    // reuse tile smem (sync above)
        if (lane == 0) red[wid] = lmax;
        __syncthreads();
        if (tid == 0) {
            float m = red[0];
            #pragma unroll
            for (int i = 1; i < 8; i++) m = fmaxf(m, red[i]);
            atomicMax(&g_maxbits[3], __float_as_uint(m));
        }
    } else {
        float scale = __uint_as_float(g_maxbits[3]) * __uint_as_float(g_maxbits[2])
                    * (1.0f / 16129.0f);
        #pragma unroll
        for (int mi = 0; mi < 4; mi++) {
            int r0 = mBase + m_w + mi * 16 + (lane >> 2);
            #pragma unroll
            for (int nj = 0; nj < 4; nj++) {
                int c0 = nBase + n_w + nj * 8 + (lane & 3) * 2;
                float b0 = bias[c0], b1 = bias[c0 + 1];
                float2 y0 = make_float2(acc[mi][nj][0] * scale + b0,
                                        acc[mi][nj][1] * scale + b1);
                float2 y1 = make_float2(acc[mi][nj][2] * scale + b0,
                                        acc[mi][nj][3] * scale + b1);
                *(float2*)&out[(size_t)r0 * NFULL + c0]       = y0;
                *(float2*)&out[(size_t)(r0 + 8) * NFULL + c0] = y1;
            }
        }
    }
}

// ---------------- launch ----------------
extern "C" void kernel_launch(void* const* d_in, const int* in_sizes, int n_in,
                              void* d_out, int out_size) {
    const float* x     = (const float*)d_in[0];
    const float* gamma = (const float*)d_in[1];
    const float* beta  = (const float*)d_in[2];
    const float* w1    = (const float*)d_in[3];
    const float* b1    = (const float*)d_in[4];
    const float* w2    = (const float*)d_in[5];
    const float* b2    = (const float*)d_in[6];
    float* out = (float*)d_out;

    const int WN4 = HID * DIM / 4;  // 1048576 float4s per weight matrix

    cudaFuncSetAttribute(k_gemm<true,  HID, DIM>,
                         cudaFuncAttributeMaxDynamicSharedMemorySize, GEMM_DYN);
    cudaFuncSetAttribute(k_gemm<false, DIM, HID>,
                         cudaFuncAttributeMaxDynamicSharedMemorySize, GEMM_DYN);

    // launch 0: weight abs-max
    k_maxabs2<<<1024, 256>>>((const float4*)w1, (const float4*)w2, WN4);
    // launch 1: LN stats + max|LN|
    k_ln<<<NROWS / 8, 256>>>(x, gamma, beta);
    // launch 2: quantize w1, w2, and LN(x)
    {
        int wblocks = 2 * WN4 / 256;                    // 8192
        int ablocks = NROWS * (DIM / 4) / 256;          // 32768
        k_quant<<<wblocks + ablocks, 256>>>((const float4*)w1, (const float4*)w2, WN4,
                                            x, gamma, beta);
    }
    // launch 3 (ncu-profiled slot): GEMM1 -> gelu -> g_act (fp32), track max|gelu|
    k_gemm<true, HID, DIM><<<dim3(HID / 128, NROWS / 128), 256, GEMM_DYN>>>(b1, nullptr);
    // launch 4: hidden quantize (streaming, 64B/thread)
    k_hquant<<<(int)(((size_t)NROWS * HID / 4) / 1024), 256>>>();
    // launch 5: GEMM2 -> d_out (fp32)
    k_gemm<false, DIM, HID><<<dim3(DIM / 128, NROWS / 128), 256, GEMM_DYN>>>(b2, out);
}

// round 12
// speedup vs baseline: 1.0760x; 1.0047x over previous
#include <cuda_runtime.h>
#include <cuda_bf16.h>
#include <math.h>
#include <stdint.h>

#define DIM   1024
#define HID   4096
#define NROWS 32768   // 4 * 8192 tokens

// ---------------- scratch (static __device__ — no allocations allowed) ----------------
__device__ __nv_bfloat16 g_w1q[(size_t)HID * DIM];    // quantized w1 codes as bf16 ints
__device__ __nv_bfloat16 g_w2q[(size_t)DIM * HID];
__device__ __nv_bfloat16 g_aq [(size_t)NROWS * DIM];  // quantized LN(x) codes
__device__ float         g_act[(size_t)NROWS * HID];  // GELU output (fp32, pre-2nd-quant)
__device__ __nv_bfloat16 g_hq [(size_t)NROWS * HID];  // quantized hidden codes
__device__ float  g_mu  [NROWS];
__device__ float  g_rstd[NROWS];
// g_maxbits starts zeroed (static init); atomicMax with identical inputs each replay is
// idempotent, so no per-call re-init is needed (graph-replay safe, deterministic).
__device__ unsigned g_maxbits[4];  // 0: max|LN|, 1: max|w1|, 2: max|w2|, 3: max|gelu|

// ---------------- small helpers ----------------
__device__ __forceinline__ float gelu_erf(float y) {
    return 0.5f * y * (1.0f + erff(y * 0.70710678118654752440f));
}

__device__ __forceinline__ unsigned smem_u32(const void* p) {
    return (unsigned)__cvta_generic_to_shared(p);
}

__device__ __forceinline__ void cpasync16(unsigned saddr, const void* gmem) {
    asm volatile("cp.async.cg.shared.global [%0], [%1], 16;\n"
                 :: "r"(saddr), "l"(__cvta_generic_to_global(gmem)));
}
#define CP_COMMIT() asm volatile("cp.async.commit_group;\n" ::: "memory")
#define CP_WAIT1()  asm volatile("cp.async.wait_group 1;\n" ::: "memory")
#define CP_WAIT0()  asm volatile("cp.async.wait_group 0;\n" ::: "memory")

// SW128 swizzle: off ^ ((off>>3)&0x70). For off = r*128 + c (c<128) this equals
// r*128 + (c ^ ((r&7)*16)); k16-slice addresses differ only by XOR ks*32.
__device__ __forceinline__ uint32_t sw128(uint32_t off) {
    return off ^ ((off >> 3) & 0x70);
}

__device__ __forceinline__ void ldsm4(unsigned* r, unsigned saddr) {
    asm volatile("ldmatrix.sync.aligned.m8n8.x4.shared.b16 {%0,%1,%2,%3}, [%4];\n"
                 : "=r"(r[0]), "=r"(r[1]), "=r"(r[2]), "=r"(r[3]) : "r"(saddr));
}

__device__ __forceinline__ void mma16816(float* c, const unsigned* a, unsigned b0, unsigned b1) {
    asm volatile(
        "mma.sync.aligned.m16n8k16.row.col.f32.bf16.bf16.f32 "
        "{%0,%1,%2,%3}, {%4,%5,%6,%7}, {%8,%9}, {%0,%1,%2,%3};\n"
        : "+f"(c[0]), "+f"(c[1]), "+f"(c[2]), "+f"(c[3])
        : "r"(a[0]), "r"(a[1]), "r"(a[2]), "r"(a[3]), "r"(b0), "r"(b1));
}

__device__ __forceinline__ __nv_bfloat16 quant_code_bf(float v, float inv_s) {
    float q = rintf(fminf(fmaxf(v * inv_s, -1.f), 1.f) * 127.f);
    return __float2bfloat16_rn(q);   // integer in [-127,127]: exact in bf16
}

// ---------------- per-tensor abs-max of BOTH weights ----------------
__global__ void __launch_bounds__(256) k_maxabs2(const float4* __restrict__ w1,
                                                 const float4* __restrict__ w2, int n4) {
    const float4* p = (blockIdx.x < gridDim.x / 2) ? w1 : w2;
    int slot = (blockIdx.x < gridDim.x / 2) ? 1 : 2;
    int b0 = (blockIdx.x < gridDim.x / 2) ? blockIdx.x : blockIdx.x - gridDim.x / 2;
    float m = 0.f;
    for (int i = b0 * blockDim.x + threadIdx.x; i < n4; i += (gridDim.x / 2) * blockDim.x) {
        float4 v = __ldcs(p + i);
        m = fmaxf(m, fmaxf(fmaxf(fabsf(v.x), fabsf(v.y)), fmaxf(fabsf(v.z), fabsf(v.w))));
    }
    #pragma unroll
    for (int o = 16; o; o >>= 1) m = fmaxf(m, __shfl_xor_sync(0xffffffffu, m, o));
    __shared__ float sm[8];
    if ((threadIdx.x & 31) == 0) sm[threadIdx.x >> 5] = m;
    __syncthreads();
    if (threadIdx.x == 0) {
        #pragma unroll
        for (int i = 1; i < 8; i++) m = fmaxf(m, sm[i]);
        m = fmaxf(m, sm[0]);
        atomicMax(&g_maxbits[slot], __float_as_uint(m));
    }
}

// ---------------- LayerNorm stats + global max|LN(x)| --------------
__global__ void __launch_bounds__(256) k_ln(const float* __restrict__ x,
                                            const float* __restrict__ gamma,
                                            const float* __restrict__ beta) {
    int t = threadIdx.x;
    int w = t >> 5;
    __shared__ float a1[8], a2[8];
    __shared__ float s_mu, s_rstd;
    float4 gm = ((const float4*)gamma)[t];
    float4 bt = ((const float4*)beta)[t];
    float gmax = 0.f;
    for (int r = 0; r < 8; r++) {
        int row = blockIdx.x * 8 + r;
        float4 v = ((const float4*)(x + (size_t)row * DIM))[t];
        float s1 = v.x + v.y + v.z + v.w;
        float s2 = v.x * v.x + v.y * v.y + v.z * v.z + v.w * v.w;
        #pragma unroll
        for (int o = 16; o; o >>= 1) {
            s1 += __shfl_xor_sync(0xffffffffu, s1, o);
            s2 += __shfl_xor_sync(0xffffffffu, s2, o);
        }
        if ((t & 31) == 0) { a1[w] = s1; a2[w] = s2; }
        __syncthreads();
        if (t == 0) {
            float S1 = 0.f, S2 = 0.f;
            #pragma unroll
            for (int i = 0; i < 8; i++) { S1 += a1[i]; S2 += a2[i]; }
            float mu   = S1 * (1.0f / DIM);
            float var  = S2 * (1.0f / DIM) - mu * mu;
            float rstd = rsqrtf(var + 1e-5f);
            s_mu = mu; s_rstd = rstd;
            g_mu[row] = mu; g_rstd[row] = rstd;
        }
        __syncthreads();
        float mu = s_mu, rs = s_rstd;
        float h0 = (v.x - mu) * rs * gm.x + bt.x;
        float h1 = (v.y - mu) * rs * gm.y + bt.y;
        float h2 = (v.z - mu) * rs * gm.z + bt.z;
        float h3 = (v.w - mu) * rs * gm.w + bt.w;
        gmax = fmaxf(gmax, fmaxf(fmaxf(fabsf(h0), fabsf(h1)), fmaxf(fabsf(h2), fabsf(h3))));
        __syncthreads();
    }
    #pragma unroll
    for (int o = 16; o; o >>= 1) gmax = fmaxf(gmax, __shfl_xor_sync(0xffffffffu, gmax, o));
    if ((t & 31) == 0) a1[w] = gmax;
    __syncthreads();
    if (t == 0) {
        float m = a1[0];
        #pragma unroll
        for (int i = 1; i < 8; i++) m = fmaxf(m, a1[i]);
        atomicMax(&g_maxbits[0], __float_as_uint(m));
    }
}

// ------- quantize BOTH weights + LN activations in ONE kernel -------
__global__ void __launch_bounds__(256) k_quant(const float4* __restrict__ w1,
                                               const float4* __restrict__ w2, int n4,
                                               const float* __restrict__ x,
                                               const float* __restrict__ gamma,
                                               const float* __restrict__ beta) {
    int i = blockIdx.x * 256 + threadIdx.x;
    if (i < 2 * n4) {
        const float4* w; __nv_bfloat16* out; int slot;
        if (i < n4) { w = w1; out = g_w1q; slot = 1; }
        else        { w = w2; out = g_w2q; slot = 2; i -= n4; }
        float inv_s = 1.0f / __uint_as_float(g_maxbits[slot]);
        float4 v = __ldcs(w + i);
        ushort4 u;
        u.x = __bfloat16_as_ushort(quant_code_bf(v.x, inv_s));
        u.y = __bfloat16_as_ushort(quant_code_bf(v.y, inv_s));
        u.z = __bfloat16_as_ushort(quant_code_bf(v.z, inv_s));
        u.w = __bfloat16_as_ushort(quant_code_bf(v.w, inv_s));
        ((ushort4*)out)[i] = u;
    } else {
        i -= 2 * n4;
        int row = i >> 8;
        int c4  = i & 255;
        float inv_s = 1.0f / __uint_as_float(g_maxbits[0]);
        float mu = g_mu[row], r = g_rstd[row];
        float4 v  = ((const float4*)x)[i];
        float4 gm = ((const float4*)gamma)[c4];
        float4 bt = ((const float4*)beta)[c4];
        ushort4 u;
        u.x = __bfloat16_as_ushort(quant_code_bf((v.x - mu) * r * gm.x + bt.x, inv_s));
        u.y = __bfloat16_as_ushort(quant_code_bf((v.y - mu) * r * gm.y + bt.y, inv_s));
        u.z = __bfloat16_as_ushort(quant_code_bf((v.z - mu) * r * gm.z + bt.z, inv_s));
        u.w = __bfloat16_as_ushort(quant_code_bf((v.w - mu) * r * gm.w + bt.w, inv_s));
        ((ushort4*)g_aq)[i] = u;
    }
}

// ------- hidden quantize (GELU fp32 -> bf16 codes), 64B/thread, with offset -------
__global__ void __launch_bounds__(256) k_hquant(size_t base4) {
    size_t b = base4 + (size_t)blockIdx.x * 1024 + threadIdx.x;   // 4 float4 per thread
    float inv_s = 1.0f / __uint_as_float(g_maxbits[3]);
    #pragma unroll
    for (int j = 0; j < 4; j++) {
        size_t i = b + (size_t)j * 256;
        float4 v = __ldcs((const float4*)g_act + i);
        ushort4 u;
        u.x = __bfloat16_as_ushort(quant_code_bf(v.x, inv_s));
        u.y = __bfloat16_as_ushort(quant_code_bf(v.y, inv_s));
        u.z = __bfloat16_as_ushort(quant_code_bf(v.z, inv_s));
        u.w = __bfloat16_as_ushort(quant_code_bf(v.w, inv_s));
        __stcs((ushort4*)g_hq + i, u);
    }
}

// ===== bf16 HMMA GEMM: CTA 128x128, warp tile 64x32, 3-stage, 2 CTAs/SM ============
#define BK 64
#define STAGE_A (128 * 128)            // 16 KB (128 rows x 128B)
#define STAGE_BYTES (2 * STAGE_A)      // A + B per stage = 32 KB
#define GEMM_DYN (3 * STAGE_BYTES)     // 96 KB

template<bool GELU, int NFULL, int K>
__global__ void __launch_bounds__(256, 2) k_gemm(const float* __restrict__ bias,
                                                 float* __restrict__ out, int mOff) {
    constexpr int KT = K / BK;
    const __nv_bfloat16* __restrict__ A = GELU ? g_aq  : g_hq;
    const __nv_bfloat16* __restrict__ B = GELU ? g_w1q : g_w2q;

    extern __shared__ uint8_t dyn[];
    const uint32_t base = smem_u32(dyn);   // dynamic smem is >=1KB aligned

    const int tid  = threadIdx.x;
    const int lane = tid & 31;
    const int wid  = tid >> 5;
    const int m_w  = (wid & 1) * 64;       // 2 warp rows of 64
    const int n_w  = (wid >> 1) * 32;      // 4 warp cols of 32
    const int mBase = mOff + blockIdx.y * 128;
    const int nBase = blockIdx.x * 128;

    const int rowBytes = K * 2;
    // per-thread loader base pointers: chunk c = tid + i*256 -> row rr + i*32, col c16
    const int rr  = tid >> 3;
    const int c16 = (tid & 7) * 16;
    const uint8_t* Agb = (const uint8_t*)(A + (size_t)mBase * K) + (size_t)rr * rowBytes + c16;
    const uint8_t* Bgb = (const uint8_t*)(B + (size_t)nBase * K) + (size_t)rr * rowBytes + c16;
    const uint32_t soff = sw128((uint32_t)rr * 128 + c16);   // same pattern each 32-row step

    float acc[4][4][4];                    // 64 regs
    #pragma unroll
    for (int i = 0; i < 4; i++)
        #pragma unroll
        for (int j = 0; j < 4; j++)
            #pragma unroll
            for (int r = 0; r < 4; r++) acc[i][j][r] = 0.f;

    auto loadTile = [&](int kt, int s) {
        uint32_t a0 = base + s * STAGE_BYTES;
        int k0b = kt * (BK * 2);
        #pragma unroll
        for (int i = 0; i < 4; i++)   // A: rows rr + i*32 (row%8 invariant -> same swizzle)
            cpasync16(a0 + soff + (uint32_t)(i * 32) * 128,
                      Agb + (size_t)(i * 32) * rowBytes + k0b);
        #pragma unroll
        for (int i = 0; i < 4; i++)   // B
            cpasync16(a0 + STAGE_A + soff + (uint32_t)(i * 32) * 128,
                      Bgb + (size_t)(i * 32) * rowBytes + k0b);
    };

    loadTile(0, 0); CP_COMMIT();
    if (KT > 1) { loadTile(1, 1); CP_COMMIT(); }

    // hoisted swizzled ldsm offsets; per-ks address = off ^ (ks*32)
    const int lr  = lane & 15;
    const uint32_t l16 = (lane >> 4) * 16;
    uint32_t a_off[4], b_off[2];
    #pragma unroll
    for (int mi = 0; mi < 4; mi++) {
        uint32_t r = m_w + mi * 16 + lr;
        a_off[mi] = r * 128 + (l16 ^ ((r & 7) * 16));
    }
    #pragma unroll
    for (int ni = 0; ni < 2; ni++) {
        uint32_t r = n_w + ni * 16 + lr;
        b_off[ni] = STAGE_A + r * 128 + (l16 ^ ((r & 7) * 16));
    }

    int stage = 0;
    for (int kt = 0; kt < KT; ++kt) {
        if (kt == KT - 1) { CP_WAIT0(); } else { CP_WAIT1(); }
        __syncthreads();   // stage kt visible; stage (kt-1)%3 compute finished
        if (kt + 2 < KT) { loadTile(kt + 2, (kt + 2) % 3); CP_COMMIT(); }

        uint32_t sb = base + stage * STAGE_BYTES;
        #pragma unroll
        for (int ks = 0; ks < 4; ++ks) {       // 4 x k16 covers BK=64
            const uint32_t xv = ks * 32;
            unsigned af[4][4], bfr[2][4];
            #pragma unroll
            for (int mi = 0; mi < 4; mi++) ldsm4(af[mi], sb + (a_off[mi] ^ xv));
            #pragma unroll
            for (int ni = 0; ni < 2; ni++) ldsm4(bfr[ni], sb + (b_off[ni] ^ xv));
            #pragma unroll
            for (int mi = 0; mi < 4; mi++)
                #pragma unroll
                for (int nj = 0; nj < 4; nj++)
                    mma16816(acc[mi][nj], af[mi],
                             bfr[nj >> 1][nj & 1], bfr[nj >> 1][2 + (nj & 1)]);
        }
        stage = (stage + 1 == 3) ? 0 : stage + 1;
    }
    __syncthreads();   // last stage compute done before smem reuse below

    // ---- epilogue ----
    if (GELU) {
        float scale = __uint_as_float(g_maxbits[0]) * __uint_as_float(g_maxbits[1])
                    * (1.0f / 16129.0f);
        float lmax = 0.f;
        #pragma unroll
        for (int mi = 0; mi < 4; mi++) {
            int r0 = mBase + m_w + mi * 16 + (lane >> 2);
            #pragma unroll
            for (int nj = 0; nj < 4; nj++) {
                int c0 = nBase + n_w + nj * 8 + (lane & 3) * 2;
                float b0 = bias[c0], b1 = bias[c0 + 1];
                float g00 = gelu_erf(acc[mi][nj][0] * scale + b0);
                float g01 = gelu_erf(acc[mi][nj][1] * scale + b1);
                float g10 = gelu_erf(acc[mi][nj][2] * scale + b0);
                float g11 = gelu_erf(acc[mi][nj][3] * scale + b1);
                lmax = fmaxf(lmax, fmaxf(fmaxf(fabsf(g00), fabsf(g01)),
                                         fmaxf(fabsf(g10), fabsf(g11))));
                __stcs((float2*)&g_act[(size_t)r0 * NFULL + c0],       make_float2(g00, g01));
                __stcs((float2*)&g_act[(size_t)(r0 + 8) * NFULL + c0], make_float2(g10, g11));
            }
        }
        #pragma unroll
        for (int o = 16; o; o >>= 1) lmax = fmaxf(lmax, __shfl_xor_sync(0xffffffffu, lmax, o));
        float* red = (float*)dyn;    // reuse tile smem (sync above)
        if (lane == 0) red[wid] = lmax;
        __syncthreads();
        if (tid == 0) {
            float m = red[0];
            #pragma unroll
            for (int i = 1; i < 8; i++) m = fmaxf(m, red[i]);
            atomicMax(&g_maxbits[3], __float_as_uint(m));
        }
    } else {
        float scale = __uint_as_float(g_maxbits[3]) * __uint_as_float(g_maxbits[2])
                    * (1.0f / 16129.0f);
        #pragma unroll
        for (int mi = 0; mi < 4; mi++) {
            int r0 = mBase + m_w + mi * 16 + (lane >> 2);
            #pragma unroll
            for (int nj = 0; nj < 4; nj++) {
                int c0 = nBase + n_w + nj * 8 + (lane & 3) * 2;
                float b0 = bias[c0], b1 = bias[c0 + 1];
                float2 y0 = make_float2(acc[mi][nj][0] * scale + b0,
                                        acc[mi][nj][1] * scale + b1);
                float2 y1 = make_float2(acc[mi][nj][2] * scale + b0,
                                        acc[mi][nj][3] * scale + b1);
                *(float2*)&out[(size_t)r0 * NFULL + c0]       = y0;
                *(float2*)&out[(size_t)(r0 + 8) * NFULL + c0] = y1;
            }
        }
    }
}

// ---------------- launch ----------------
extern "C" void kernel_launch(void* const* d_in, const int* in_sizes, int n_in,
                              void* d_out, int out_size) {
    const float* x     = (const float*)d_in[0];
    const float* gamma = (const float*)d_in[1];
    const float* beta  = (const float*)d_in[2];
    const float* w1    = (const float*)d_in[3];
    const float* b1    = (const float*)d_in[4];
    const float* w2    = (const float*)d_in[5];
    const float* b2    = (const float*)d_in[6];
    float* out = (float*)d_out;

    const int WN4 = HID * DIM / 4;  // 1048576 float4s per weight matrix

    // Streams/events created once on the (uncaptured) correctness call; reused during
    // graph capture. Fork/join via events becomes graph dependencies. Launch sequence
    // is identical on every call (no work is skipped).
    static cudaStream_t s2 = nullptr;
    static cudaEvent_t evF = nullptr, evW = nullptr, ev0 = nullptr, evG = nullptr;
    if (!s2) {
        cudaStreamCreateWithFlags(&s2, cudaStreamNonBlocking);
        cudaEventCreateWithFlags(&evF, cudaEventDisableTiming);
        cudaEventCreateWithFlags(&evW, cudaEventDisableTiming);
        cudaEventCreateWithFlags(&ev0, cudaEventDisableTiming);
        cudaEventCreateWithFlags(&evG, cudaEventDisableTiming);
        cudaFuncSetAttribute(k_gemm<true,  HID, DIM>,
                             cudaFuncAttributeMaxDynamicSharedMemorySize, GEMM_DYN);
        cudaFuncSetAttribute(k_gemm<false, DIM, HID>,
                             cudaFuncAttributeMaxDynamicSharedMemorySize, GEMM_DYN);
    }

    // ---- fork: weight abs-max on s2 concurrent with LN on null ----
    cudaEventRecord(evF, 0);
    cudaStreamWaitEvent(s2, evF, 0);
    k_maxabs2<<<1024, 256, 0, s2>>>((const float4*)w1, (const float4*)w2, WN4);
    cudaEventRecord(evW, s2);

    k_ln<<<NROWS / 8, 256>>>(x, gamma, beta);
    cudaStreamWaitEvent(0, evW, 0);   // join: quant needs weight maxes + LN stats

    {
        int wblocks = 2 * WN4 / 256;                    // 8192
        int ablocks = NROWS * (DIM / 4) / 256;          // 32768
        k_quant<<<wblocks + ablocks, 256>>>((const float4*)w1, (const float4*)w2, WN4,
                                            x, gamma, beta);
    }

    // GEMM1 (full M) -> gelu -> g_act (fp32), track max|gelu|
    k_gemm<true, HID, DIM><<<dim3(HID / 128, NROWS / 128), 256, GEMM_DYN>>>(b1, nullptr, 0);

    // ---- hquant/GEMM2 split in M halves; GEMM2(half0) overlaps hquant(half1) ----
    const int MH = NROWS / 2;                                  // 16384 rows per half
    const size_t HQ4 = (size_t)MH * HID / 4;                   // float4s per half
    const int HQBLK = (int)(HQ4 / 1024);                       // 16384 blocks per half

    k_hquant<<<HQBLK, 256>>>(0);                               // null: half0
    cudaEventRecord(ev0, 0);
    cudaStreamWaitEvent(s2, ev0, 0);
    k_gemm<false, DIM, HID><<<dim3(DIM / 128, MH / 128), 256, GEMM_DYN, s2>>>(b2, out, 0);
    cudaEventRecord(evG, s2);

    k_hquant<<<HQBLK, 256>>>(HQ4);                             // null: half1 (concurrent)
    k_gemm<false, DIM, HID><<<dim3(DIM / 128, MH / 128), 256, GEMM_DYN>>>(b2, out, MH);

    cudaStreamWaitEvent(0, evG, 0);   // join s2 back into the capture stream
}